// round 15
// baseline (speedup 1.0000x reference)
#include <cuda_runtime.h>
#include <cuda_bf16.h>
#include <cuda_fp16.h>
#include <cstdint>

// ---------------- problem constants ----------------
#define MAXN 100000
#define MAXE 1600000
#define NEG_SLOPE 0.2f

// ---------------- scratch ----------------
__device__ __half g_fs16[(size_t)MAXN * 192];
__device__ float g_h [(size_t)MAXN * 128];
__device__ float g_el[(size_t)MAXN * 4];
__device__ float g_er[(size_t)MAXN * 4];
__device__ float g_wdr[256 * 4];
__device__ int   g_deg[MAXN];
__device__ int   g_rowptr[MAXN + 1];
__device__ int   g_cursor[MAXN];
__device__ int   g_srcs[MAXE];
__device__ int   g_bsum[256];
__device__ __half g_a16[(size_t)MAXN * 256];
__device__ __half g_w16[192 * 256];

// ---------------- helpers ----------------
__device__ __forceinline__ uint32_t smem_u32(const void* p) {
    uint32_t a;
    asm("{ .reg .u64 t; cvta.to.shared.u64 t, %1; cvt.u32.u64 %0, t; }" : "=r"(a) : "l"(p));
    return a;
}
__device__ __forceinline__ void cp16(uint32_t dst, const void* src, bool pred) {
    int sz = pred ? 16 : 0;
    asm volatile("cp.async.cg.shared.global [%0], [%1], 16, %2;" :: "r"(dst), "l"(src), "r"(sz));
}
#define CP_COMMIT() asm volatile("cp.async.commit_group;" ::: "memory")
#define CP_WAIT(N)  asm volatile("cp.async.wait_group %0;" :: "n"(N) : "memory")

// ---------------- prep: CSR build ----------------
__global__ void zero_i32(int* p, int n) {
    int i = blockIdx.x * blockDim.x + threadIdx.x;
    if (i < n) p[i] = 0;
}

__global__ void hist4_kernel(const int* __restrict__ dst, int* __restrict__ deg, int E) {
    int i = (blockIdx.x * blockDim.x + threadIdx.x) * 4;
    if (i + 3 < E) {
        int4 d = *(const int4*)(dst + i);
        atomicAdd(&deg[d.x], 1);
        atomicAdd(&deg[d.y], 1);
        atomicAdd(&deg[d.z], 1);
        atomicAdd(&deg[d.w], 1);
    } else {
        for (int j = i; j < E; j++) atomicAdd(&deg[dst[j]], 1);
    }
}

__global__ void scan_reduce(const int* __restrict__ deg, int* __restrict__ bsum, int n) {
    __shared__ int sh[256];
    int tid = threadIdx.x;
    int base = blockIdx.x * 1024;
    int s = 0;
    for (int i = tid; i < 1024; i += 256) {
        int g = base + i;
        s += (g < n) ? deg[g] : 0;
    }
    sh[tid] = s; __syncthreads();
    for (int off = 128; off; off >>= 1) {
        if (tid < off) sh[tid] += sh[tid + off];
        __syncthreads();
    }
    if (tid == 0) bsum[blockIdx.x] = sh[0];
}

__global__ void scan_bsums(int* __restrict__ bsum, int B, int* __restrict__ rowptr, int n, int E) {
    __shared__ int sh[256];
    int tid = threadIdx.x;
    int v = (tid < B) ? bsum[tid] : 0;
    sh[tid] = v; __syncthreads();
    for (int off = 1; off < 256; off <<= 1) {
        int t = (tid >= off) ? sh[tid - off] : 0;
        __syncthreads();
        sh[tid] += t;
        __syncthreads();
    }
    if (tid < B) bsum[tid] = sh[tid] - v;
    if (tid == 0) rowptr[n] = E;
}

__global__ void scan_write(const int* __restrict__ deg, const int* __restrict__ boff,
                           int* __restrict__ rowptr, int* __restrict__ cursor, int n) {
    __shared__ int sh[256];
    int tid = threadIdx.x;
    int base = blockIdx.x * 1024 + tid * 4;
    int v[4]; int tsum = 0;
#pragma unroll
    for (int j = 0; j < 4; j++) {
        int g = base + j;
        v[j] = (g < n) ? deg[g] : 0;
        tsum += v[j];
    }
    sh[tid] = tsum; __syncthreads();
    for (int off = 1; off < 256; off <<= 1) {
        int t = (tid >= off) ? sh[tid - off] : 0;
        __syncthreads();
        sh[tid] += t;
        __syncthreads();
    }
    int run = boff[blockIdx.x] + sh[tid] - tsum;
#pragma unroll
    for (int j = 0; j < 4; j++) {
        int g = base + j;
        if (g < n) { rowptr[g] = run; cursor[g] = run; }
        run += v[j];
    }
}

__global__ void scatter4_kernel(const int* __restrict__ src, const int* __restrict__ dst,
                                int* __restrict__ cursor, int* __restrict__ srcs, int E) {
    int i = (blockIdx.x * blockDim.x + threadIdx.x) * 4;
    if (i + 3 < E) {
        int4 d = *(const int4*)(dst + i);
        int4 s = *(const int4*)(src + i);
        srcs[atomicAdd(&cursor[d.x], 1)] = s.x;
        srcs[atomicAdd(&cursor[d.y], 1)] = s.y;
        srcs[atomicAdd(&cursor[d.z], 1)] = s.z;
        srcs[atomicAdd(&cursor[d.w], 1)] = s.w;
    } else {
        for (int j = i; j < E; j++) {
            int p = atomicAdd(&cursor[dst[j]], 1);
            srcs[p] = src[j];
        }
    }
}

// ---------------- fp16 pack kernels ----------------
__global__ void packA16(const float* __restrict__ A, __half* __restrict__ A16, int total2) {
    int i = blockIdx.x * blockDim.x + threadIdx.x;
    if (i >= total2) return;
    float2 v = ((const float2*)A)[i];
    ((__half2*)A16)[i] = __floats2half2_rn(v.x, v.y);
}

__global__ void packW16(const float* __restrict__ W, __half* __restrict__ W16,
                        int K, int Ncols, int Npad, int interleave48) {
    int i = blockIdx.x * blockDim.x + threadIdx.x;
    if (i >= Npad * K) return;
    int r = i / K, c = i % K;
    int srcCol; bool valid;
    if (interleave48) {
        int hh = r / 48, cc = r % 48;
        srcCol = hh * 47 + cc;
        valid = (cc < 47);
    } else {
        srcCol = r;
        valid = (r < Ncols);
    }
    float v = valid ? W[(size_t)c * Ncols + srcCol] : 0.f;
    W16[i] = __float2half_rn(v);
}

// ---------------- mma.sync fp16 GEMM, 4-stage cp.async pipeline ----------------
#define MMA_F16(c, a, b0, b1) \
    asm volatile("mma.sync.aligned.m16n8k16.row.col.f32.f16.f16.f32 " \
        "{%0,%1,%2,%3},{%4,%5,%6,%7},{%8,%9},{%0,%1,%2,%3};" \
        : "+f"((c)[0]), "+f"((c)[1]), "+f"((c)[2]), "+f"((c)[3]) \
        : "r"((a)[0]), "r"((a)[1]), "r"((a)[2]), "r"((a)[3]), "r"(b0), "r"(b1))

template <int NPAD, int MINB>
__global__ __launch_bounds__(256, MINB)
void mma_gemm(const __half* __restrict__ A16, const __half* __restrict__ B16,
              __half* __restrict__ C16, int n, int K, int Ncols) {
    constexpr int STR = 40;
    constexpr int NT = NPAD / 16;
    constexpr int BUFU = (128 + NPAD) * STR;   // ushorts per buffer
    extern __shared__ unsigned short sm[];
    const uint32_t sbase = smem_u32(sm);

    const int tid = threadIdx.x;
    const int warp = tid >> 5;
    const int lane = tid & 31;
    const int g = lane >> 2;
    const int t = lane & 3;
    const int wm = (warp >> 1) * 32;
    const int wn = (warp & 1) * (NPAD / 2);
    const int row0 = blockIdx.x * 128;

    float acc[2][NT][4] = {};
    const int nchunks = K >> 5;

    auto load_chunk = [&](int buf, int kc) {
        uint32_t bb = sbase + (uint32_t)buf * BUFU * 2;
#pragma unroll
        for (int i2 = 0; i2 < 2; i2++) {
            int i = tid + i2 * 256;
            int r = i >> 2, q = i & 3;
            int gr = row0 + r;
            bool ok = gr < n;
            size_t off = (size_t)(ok ? gr : 0) * K + (size_t)kc * 32 + q * 8;
            cp16(bb + (uint32_t)(r * STR + q * 8) * 2, A16 + off, ok);
        }
#pragma unroll
        for (int i2 = 0; i2 < NPAD / 64; i2++) {
            int i = tid + i2 * 256;
            int r = i >> 2, q = i & 3;
            size_t off = (size_t)r * K + (size_t)kc * 32 + q * 8;
            cp16(bb + (uint32_t)(5120 + r * STR + q * 8) * 2, B16 + off, true);
        }
        CP_COMMIT();
    };

    // prologue: 3 chunks in flight (nchunks >= 4 always: K is 128 or 256)
    load_chunk(0, 0);
    load_chunk(1, 1);
    load_chunk(2, 2);

    for (int kc = 0; kc < nchunks; kc++) {
        if (kc + 3 < nchunks) load_chunk((kc + 3) & 3, kc + 3);
        else CP_COMMIT();                      // empty group keeps pending-count exact
        CP_WAIT(3);
        __syncthreads();

        const unsigned short* As = sm + (kc & 3) * BUFU;
        const unsigned short* Bs = As + 5120;

#pragma unroll
        for (int kk = 0; kk < 32; kk += 16) {
            uint32_t a[2][4];
#pragma unroll
            for (int mt = 0; mt < 2; mt++) {
                int base = (wm + mt * 16 + g) * STR + kk + t * 2;
                a[mt][0] = *(const uint32_t*)&As[base];
                a[mt][1] = *(const uint32_t*)&As[base + 8 * STR];
                a[mt][2] = *(const uint32_t*)&As[base + 8];
                a[mt][3] = *(const uint32_t*)&As[base + 8 * STR + 8];
            }
#pragma unroll
            for (int j = 0; j < NT; j++) {
                int nb = (wn + j * 8 + g) * STR + kk + t * 2;
                uint32_t b0 = *(const uint32_t*)&Bs[nb];
                uint32_t b1 = *(const uint32_t*)&Bs[nb + 8];
#pragma unroll
                for (int mt = 0; mt < 2; mt++) {
                    MMA_F16(acc[mt][j], a[mt], b0, b1);
                }
            }
        }
        __syncthreads();
    }

#pragma unroll
    for (int mt = 0; mt < 2; mt++) {
#pragma unroll
        for (int j = 0; j < NT; j++) {
            int r1 = row0 + wm + mt * 16 + g;
            int r2 = r1 + 8;
            int c = wn + j * 8 + t * 2;
            if (c < Ncols) {
                if (r1 < n) *(__half2*)(C16 + (size_t)r1 * Ncols + c)
                    = __floats2half2_rn(acc[mt][j][0], acc[mt][j][1]);
                if (r2 < n) *(__half2*)(C16 + (size_t)r2 * Ncols + c)
                    = __floats2half2_rn(acc[mt][j][2], acc[mt][j][3]);
            }
        }
    }
}

// ---------------- attention scalars ----------------
__global__ void wdr_kernel(const float* __restrict__ Wd, const float* __restrict__ ar,
                           float* __restrict__ wdr, int K, int D) {
    int idx = blockIdx.x * blockDim.x + threadIdx.x;
    if (idx >= K * 4) return;
    int k = idx >> 2, h = idx & 3;
    float s = 0.f;
    const float* wrow = Wd + (size_t)k * (4 * D) + h * D;
    const float* arow = ar + h * D;
    for (int d = 0; d < D; d++) s += wrow[d] * arow[d];
    wdr[k * 4 + h] = s;
}

__global__ void el32_kernel(const __half* __restrict__ fs16, const float* __restrict__ al,
                            float* __restrict__ el, int n) {
    int idx = blockIdx.x * blockDim.x + threadIdx.x;
    if (idx >= n * 4) return;
    int nn = idx >> 2, h = idx & 3;
    const uint2* p = (const uint2*)(fs16 + (size_t)nn * 128 + h * 32);
    const float4* a = (const float4*)(al + h * 32);
    float s = 0.f;
#pragma unroll
    for (int q = 0; q < 8; q++) {
        uint2 raw = p[q];
        float2 f0 = __half22float2(*(__half2*)&raw.x);
        float2 f1 = __half22float2(*(__half2*)&raw.y);
        float4 av = a[q];
        s += f0.x * av.x + f0.y * av.y + f1.x * av.z + f1.y * av.w;
    }
    el[idx] = s;
}

__global__ void el47_kernel(const __half* __restrict__ fs16, const float* __restrict__ al,
                            float* __restrict__ el, int n) {
    int idx = blockIdx.x * blockDim.x + threadIdx.x;
    if (idx >= n * 4) return;
    int nn = idx >> 2, h = idx & 3;
    const __half* p = fs16 + (size_t)nn * 192 + h * 48;
    const float* a = al + h * 47;
    float s = 0.f;
#pragma unroll
    for (int d = 0; d < 47; d++) s += __half2float(p[d]) * a[d];
    el[idx] = s;
}

__global__ void er_kernel(const float* __restrict__ hmat, const float* __restrict__ wdr,
                          float* __restrict__ er, int n, int K) {
    int wid = (blockIdx.x * blockDim.x + threadIdx.x) >> 5;
    int lane = threadIdx.x & 31;
    if (wid >= n) return;
    const float* hp = hmat + (size_t)wid * K;
    float a0 = 0, a1 = 0, a2 = 0, a3 = 0;
    for (int k = lane; k < K; k += 32) {
        float hv = hp[k];
        float4 w = ((const float4*)wdr)[k];
        a0 += hv * w.x; a1 += hv * w.y; a2 += hv * w.z; a3 += hv * w.w;
    }
#pragma unroll
    for (int off = 16; off; off >>= 1) {
        a0 += __shfl_xor_sync(0xffffffffu, a0, off);
        a1 += __shfl_xor_sync(0xffffffffu, a1, off);
        a2 += __shfl_xor_sync(0xffffffffu, a2, off);
        a3 += __shfl_xor_sync(0xffffffffu, a3, off);
    }
    if (lane == 0) {
        float4* o = (float4*)(er + (size_t)wid * 4);
        *o = make_float4(a0, a1, a2, a3);
    }
}

// ---------------- fused edge aggregation: 2 edges per warp iteration ----------------
__global__ __launch_bounds__(256)
void agg_fused(const __half* __restrict__ fs16, const float* __restrict__ el,
               const float* __restrict__ er, const int* __restrict__ rowptr,
               const int* __restrict__ srcs, const float* __restrict__ bias,
               float* __restrict__ out, __half* __restrict__ oh, int n) {
    int node = blockIdx.x * 8 + (threadIdx.x >> 5);
    if (node >= n) return;
    int lane = threadIdx.x & 31;
    int half_ = lane >> 4;
    int sub = lane & 15;
    int h = sub >> 2;
    int s0 = rowptr[node], s1 = rowptr[node + 1];
    float ern = __ldg(&er[node * 4 + h]);
    float acc[8] = {};
    float den = 0.f;
    for (int base = s0; base < s1; base += 32) {
        int idx = base + lane;
        int sv = (idx < s1) ? __ldg(&srcs[idx]) : 0;
        int cnt = s1 - base; if (cnt > 32) cnt = 32;
        for (int i = 0; i < cnt; i += 8) {
#pragma unroll
            for (int u = 0; u < 8; u += 2) {
                int j = i + u + half_;
                bool ok = j < cnt;
                int s = __shfl_sync(0xffffffffu, sv, j & 31);
                if (!ok) s = 0;
                float ee = __ldg(&el[s * 4 + h]) + ern;
                ee = ee > 0.f ? ee : NEG_SLOPE * ee;
                float w = ok ? __expf(ee) : 0.f;
                den += w;
                uint4 raw = __ldg((const uint4*)(fs16 + (size_t)s * 128) + sub);
                float2 f0 = __half22float2(*(__half2*)&raw.x);
                float2 f1 = __half22float2(*(__half2*)&raw.y);
                float2 f2 = __half22float2(*(__half2*)&raw.z);
                float2 f3 = __half22float2(*(__half2*)&raw.w);
                acc[0] += w * f0.x; acc[1] += w * f0.y;
                acc[2] += w * f1.x; acc[3] += w * f1.y;
                acc[4] += w * f2.x; acc[5] += w * f2.y;
                acc[6] += w * f3.x; acc[7] += w * f3.y;
            }
        }
    }
    den += __shfl_xor_sync(0xffffffffu, den, 16);
#pragma unroll
    for (int k = 0; k < 8; k++) acc[k] += __shfl_xor_sync(0xffffffffu, acc[k], 16);
    float inv = (s1 > s0) ? (1.f / den) : 0.f;
    if (lane < 16) {
        const float* bp = bias + sub * 8;
        float o[8];
#pragma unroll
        for (int k = 0; k < 8; k++) o[k] = fmaxf(acc[k] * inv + __ldg(&bp[k]), 0.f);
        float4* hb = (float4*)(out + (size_t)node * 128 + sub * 8);
        hb[0] = make_float4(o[0], o[1], o[2], o[3]);
        hb[1] = make_float4(o[4], o[5], o[6], o[7]);
        __half2 u0 = __floats2half2_rn(o[0], o[1]);
        __half2 u1 = __floats2half2_rn(o[2], o[3]);
        __half2 u2 = __floats2half2_rn(o[4], o[5]);
        __half2 u3 = __floats2half2_rn(o[6], o[7]);
        uint4 pack;
        pack.x = *(uint32_t*)&u0; pack.y = *(uint32_t*)&u1;
        pack.z = *(uint32_t*)&u2; pack.w = *(uint32_t*)&u3;
        *(uint4*)(oh + (size_t)node * 128 + sub * 8) = pack;
    }
}

// ---------------- layer 2: 2 edges/warp iter, 16 lanes/edge, 12 halves/lane ----------------
__global__ __launch_bounds__(256)
void agg_final2(const __half* __restrict__ fs16, const float* __restrict__ el,
                const float* __restrict__ er, const int* __restrict__ rowptr,
                const int* __restrict__ srcs, const float* __restrict__ b2,
                float* __restrict__ out, int n) {
    int node = blockIdx.x * 8 + (threadIdx.x >> 5);
    if (node >= n) return;
    int lane = threadIdx.x & 31;
    int half_ = lane >> 4;
    int sub = lane & 15;
    int h = sub >> 2;
    int s0 = rowptr[node], s1 = rowptr[node + 1];
    float ern = __ldg(&er[node * 4 + h]);
    float acc[12] = {};
    float den = 0.f;
    for (int base = s0; base < s1; base += 32) {
        int idx = base + lane;
        int sv = (idx < s1) ? __ldg(&srcs[idx]) : 0;
        int cnt = s1 - base; if (cnt > 32) cnt = 32;
        for (int i = 0; i < cnt; i += 4) {
#pragma unroll
            for (int u = 0; u < 4; u += 2) {
                int j = i + u + half_;
                bool ok = j < cnt;
                int s = __shfl_sync(0xffffffffu, sv, j & 31);
                if (!ok) s = 0;
                float ee = __ldg(&el[s * 4 + h]) + ern;
                ee = ee > 0.f ? ee : NEG_SLOPE * ee;
                float w = ok ? __expf(ee) : 0.f;
                den += w;
                const uint2* p = (const uint2*)(fs16 + (size_t)s * 192 + sub * 12);
                uint2 q0 = __ldg(p), q1 = __ldg(p + 1), q2 = __ldg(p + 2);
                float2 f;
                f = __half22float2(*(__half2*)&q0.x); acc[0] += w * f.x; acc[1] += w * f.y;
                f = __half22float2(*(__half2*)&q0.y); acc[2] += w * f.x; acc[3] += w * f.y;
                f = __half22float2(*(__half2*)&q1.x); acc[4] += w * f.x; acc[5] += w * f.y;
                f = __half22float2(*(__half2*)&q1.y); acc[6] += w * f.x; acc[7] += w * f.y;
                f = __half22float2(*(__half2*)&q2.x); acc[8] += w * f.x; acc[9] += w * f.y;
                f = __half22float2(*(__half2*)&q2.y); acc[10] += w * f.x; acc[11] += w * f.y;
            }
        }
    }
    den += __shfl_xor_sync(0xffffffffu, den, 16);
#pragma unroll
    for (int k = 0; k < 12; k++) acc[k] += __shfl_xor_sync(0xffffffffu, acc[k], 16);
    float inv = (s1 > s0) ? (1.f / den) : 0.f;
    int cbase = (sub & 3) * 12;
    float v[12];
#pragma unroll
    for (int k = 0; k < 12; k++) {
        int c = cbase + k;
        v[k] = acc[k] * inv + ((c < 47) ? __ldg(&b2[h * 47 + c]) : 0.f);
    }
#pragma unroll
    for (int k = 0; k < 12; k++) {
        v[k] += __shfl_xor_sync(0xffffffffu, v[k], 4);
        v[k] += __shfl_xor_sync(0xffffffffu, v[k], 8);
        v[k] *= 0.25f;
    }
    float mx = -1e30f;
#pragma unroll
    for (int k = 0; k < 12; k++)
        if (cbase + k < 47) mx = fmaxf(mx, v[k]);
    mx = fmaxf(mx, __shfl_xor_sync(0xffffffffu, mx, 1));
    mx = fmaxf(mx, __shfl_xor_sync(0xffffffffu, mx, 2));
    float se = 0.f;
#pragma unroll
    for (int k = 0; k < 12; k++)
        if (cbase + k < 47) se += __expf(v[k] - mx);
    se += __shfl_xor_sync(0xffffffffu, se, 1);
    se += __shfl_xor_sync(0xffffffffu, se, 2);
    float l = logf(se) + mx;
    if (lane < 4) {
        float* op = out + (size_t)node * 47;
#pragma unroll
        for (int k = 0; k < 12; k++) {
            int c = cbase + k;
            if (c < 47) op[c] = v[k] - l;
        }
    }
}

// ---------------- launch (stream-forked DAG) ----------------
extern "C" void kernel_launch(void* const* d_in, const int* in_sizes, int n_in,
                              void* d_out, int out_size) {
    const float* x   = (const float*)d_in[0];
    const int*   src = (const int*)d_in[1];
    const int*   dst = (const int*)d_in[2];
    const float* W0s = (const float*)d_in[3];
    const float* W0d = (const float*)d_in[4];
    const float* a0l = (const float*)d_in[5];
    const float* a0r = (const float*)d_in[6];
    const float* b0  = (const float*)d_in[7];
    const float* W1s = (const float*)d_in[8];
    const float* W1d = (const float*)d_in[9];
    const float* a1l = (const float*)d_in[10];
    const float* a1r = (const float*)d_in[11];
    const float* b1  = (const float*)d_in[12];
    const float* W2s = (const float*)d_in[13];
    const float* W2d = (const float*)d_in[14];
    const float* a2l = (const float*)d_in[15];
    const float* a2r = (const float*)d_in[16];
    const float* b2  = (const float*)d_in[17];

    int n = in_sizes[0] / 256;
    int E = in_sizes[1];
    float* out = (float*)d_out;

    float *hbuf, *el, *er, *wdr;
    __half *fs16, *a16, *w16;
    int *deg, *rowptr, *cursor, *srcs, *bsum;
    cudaGetSymbolAddress((void**)&fs16,   g_fs16);
    cudaGetSymbolAddress((void**)&hbuf,   g_h);
    cudaGetSymbolAddress((void**)&el,     g_el);
    cudaGetSymbolAddress((void**)&er,     g_er);
    cudaGetSymbolAddress((void**)&wdr,    g_wdr);
    cudaGetSymbolAddress((void**)&deg,    g_deg);
    cudaGetSymbolAddress((void**)&rowptr, g_rowptr);
    cudaGetSymbolAddress((void**)&cursor, g_cursor);
    cudaGetSymbolAddress((void**)&srcs,   g_srcs);
    cudaGetSymbolAddress((void**)&bsum,   g_bsum);
    cudaGetSymbolAddress((void**)&a16,    g_a16);
    cudaGetSymbolAddress((void**)&w16,    g_w16);

    const int smem128 = 4 * (128 + 128) * 40 * 2;  // 81920 B
    const int smem192 = 4 * (128 + 192) * 40 * 2;  // 102400 B
    cudaFuncSetAttribute((const void*)mma_gemm<128, 2>,
                         cudaFuncAttributeMaxDynamicSharedMemorySize, smem128);
    cudaFuncSetAttribute((const void*)mma_gemm<192, 2>,
                         cudaFuncAttributeMaxDynamicSharedMemorySize, smem192);

    int gemmBlocks = (n + 127) / 128;
    int nodeBlocks = (n + 7) / 8;
    int nb = (n + 1023) / 1024;
    int e4Blocks = (E / 4 + 255) / 256;

    // side stream + events
    cudaStream_t sB;
    cudaStreamCreate(&sB);
    cudaEvent_t evFork, evWdr0, evSide0, evG0, evW1, evG1, evEr1s, evAgg1, evW2, evEr2s;
    cudaEventCreateWithFlags(&evFork,  cudaEventDisableTiming);
    cudaEventCreateWithFlags(&evWdr0,  cudaEventDisableTiming);
    cudaEventCreateWithFlags(&evSide0, cudaEventDisableTiming);
    cudaEventCreateWithFlags(&evG0,    cudaEventDisableTiming);
    cudaEventCreateWithFlags(&evW1,    cudaEventDisableTiming);
    cudaEventCreateWithFlags(&evG1,    cudaEventDisableTiming);
    cudaEventCreateWithFlags(&evEr1s,  cudaEventDisableTiming);
    cudaEventCreateWithFlags(&evAgg1,  cudaEventDisableTiming);
    cudaEventCreateWithFlags(&evW2,    cudaEventDisableTiming);
    cudaEventCreateWithFlags(&evEr2s,  cudaEventDisableTiming);

    // ---- fork ----
    cudaEventRecord(evFork, 0);
    cudaStreamWaitEvent(sB, evFork, 0);

    // main: layer-0 dense chain
    wdr_kernel<<<(256 * 4 + 255) / 256, 256>>>(W0d, a0r, wdr, 256, 32);
    cudaEventRecord(evWdr0, 0);
    packA16<<<(n * 256 / 2 + 255) / 256, 256>>>(x, a16, n * 256 / 2);
    packW16<<<(128 * 256 + 255) / 256, 256>>>(W0s, w16, 256, 128, 128, 0);
    mma_gemm<128, 2><<<gemmBlocks, 256, smem128>>>(a16, w16, fs16, n, 256, 128);
    cudaEventRecord(evG0, 0);
    el32_kernel<<<(n * 4 + 255) / 256, 256>>>(fs16, a0l, el, n);

    // side: CSR build, then er0
    zero_i32<<<(n + 255) / 256, 256, 0, sB>>>(deg, n);
    hist4_kernel<<<e4Blocks, 256, 0, sB>>>(dst, deg, E);
    scan_reduce<<<nb, 256, 0, sB>>>(deg, bsum, n);
    scan_bsums<<<1, 256, 0, sB>>>(bsum, nb, rowptr, n, E);
    scan_write<<<nb, 256, 0, sB>>>(deg, bsum, rowptr, cursor, n);
    scatter4_kernel<<<e4Blocks, 256, 0, sB>>>(src, dst, cursor, srcs, E);
    cudaStreamWaitEvent(sB, evWdr0, 0);
    er_kernel<<<nodeBlocks, 256, 0, sB>>>(x, wdr, er, n, 256);
    cudaEventRecord(evSide0, sB);

    // side: layer-1 weight prep (after gemm0 frees w16)
    cudaStreamWaitEvent(sB, evG0, 0);
    wdr_kernel<<<(128 * 4 + 255) / 256, 256, 0, sB>>>(W1d, a1r, wdr, 128, 32);
    packW16<<<(128 * 128 + 255) / 256, 256, 0, sB>>>(W1s, w16, 128, 128, 128, 0);
    cudaEventRecord(evW1, sB);

    // main: join, agg0
    cudaStreamWaitEvent(0, evSide0, 0);
    agg_fused<<<nodeBlocks, 256>>>(fs16, el, er, rowptr, srcs, b0, hbuf, a16, n);

    // ---- layer 1 ----
    cudaStreamWaitEvent(0, evW1, 0);
    mma_gemm<128, 2><<<gemmBlocks, 256, smem128>>>(a16, w16, fs16, n, 128, 128);
    cudaEventRecord(evG1, 0);
    el32_kernel<<<(n * 4 + 255) / 256, 256>>>(fs16, a1l, el, n);

    // side: er1, then layer-2 weight prep
    cudaStreamWaitEvent(sB, evG1, 0);
    er_kernel<<<nodeBlocks, 256, 0, sB>>>(hbuf, wdr, er, n, 128);
    cudaEventRecord(evEr1s, sB);
    wdr_kernel<<<(128 * 4 + 255) / 256, 256, 0, sB>>>(W2d, a2r, wdr, 128, 47);
    packW16<<<(192 * 128 + 255) / 256, 256, 0, sB>>>(W2s, w16, 128, 188, 192, 1);
    cudaEventRecord(evW2, sB);

    // main: join er1, agg1
    cudaStreamWaitEvent(0, evEr1s, 0);
    agg_fused<<<nodeBlocks, 256>>>(fs16, el, er, rowptr, srcs, b1, hbuf, a16, n);
    cudaEventRecord(evAgg1, 0);

    // side: er2 concurrent with gemm2/el47
    cudaStreamWaitEvent(sB, evAgg1, 0);
    er_kernel<<<nodeBlocks, 256, 0, sB>>>(hbuf, wdr, er, n, 128);
    cudaEventRecord(evEr2s, sB);

    // ---- layer 2 ----
    cudaStreamWaitEvent(0, evW2, 0);
    mma_gemm<192, 2><<<gemmBlocks, 256, smem192>>>(a16, w16, fs16, n, 128, 192);
    el47_kernel<<<(n * 4 + 255) / 256, 256>>>(fs16, a2l, el, n);
    cudaStreamWaitEvent(0, evEr2s, 0);
    agg_final2<<<nodeBlocks, 256>>>(fs16, el, er, rowptr, srcs, b2, out, n);

    cudaEventDestroy(evFork);
    cudaEventDestroy(evWdr0);
    cudaEventDestroy(evSide0);
    cudaEventDestroy(evG0);
    cudaEventDestroy(evW1);
    cudaEventDestroy(evG1);
    cudaEventDestroy(evEr1s);
    cudaEventDestroy(evAgg1);
    cudaEventDestroy(evW2);
    cudaEventDestroy(evEr2s);
    cudaStreamDestroy(sB);
}

// round 16
// speedup vs baseline: 1.0644x; 1.0644x over previous
#include <cuda_runtime.h>
#include <cuda_bf16.h>
#include <cuda_fp16.h>
#include <cstdint>

// ---------------- problem constants ----------------
#define MAXN 100000
#define MAXE 1600000
#define NEG_SLOPE 0.2f

// ---------------- scratch ----------------
__device__ __half g_fs16[(size_t)MAXN * 192];
__device__ float g_h [(size_t)MAXN * 128];
__device__ float g_el[(size_t)MAXN * 4];
__device__ float g_er[(size_t)MAXN * 4];
__device__ float g_wdr[256 * 4];
__device__ float g_alp[192];
__device__ int   g_deg[MAXN];
__device__ int   g_rowptr[MAXN + 1];
__device__ int   g_cursor[MAXN];
__device__ int   g_srcs[MAXE];
__device__ int   g_bsum[256];
__device__ __half g_a16[(size_t)MAXN * 256];
__device__ __half g_w16[192 * 256];

// ---------------- helpers ----------------
__device__ __forceinline__ uint32_t smem_u32(const void* p) {
    uint32_t a;
    asm("{ .reg .u64 t; cvta.to.shared.u64 t, %1; cvt.u32.u64 %0, t; }" : "=r"(a) : "l"(p));
    return a;
}
__device__ __forceinline__ void cp16(uint32_t dst, const void* src, bool pred) {
    int sz = pred ? 16 : 0;
    asm volatile("cp.async.cg.shared.global [%0], [%1], 16, %2;" :: "r"(dst), "l"(src), "r"(sz));
}
#define CP_COMMIT() asm volatile("cp.async.commit_group;" ::: "memory")
#define CP_WAIT(N)  asm volatile("cp.async.wait_group %0;" :: "n"(N) : "memory")

// ---------------- prep: CSR build ----------------
__global__ void zero_i32(int* p, int n) {
    int i = blockIdx.x * blockDim.x + threadIdx.x;
    if (i < n) p[i] = 0;
}

__global__ void hist4_kernel(const int* __restrict__ dst, int* __restrict__ deg, int E) {
    int i = (blockIdx.x * blockDim.x + threadIdx.x) * 4;
    if (i + 3 < E) {
        int4 d = *(const int4*)(dst + i);
        atomicAdd(&deg[d.x], 1);
        atomicAdd(&deg[d.y], 1);
        atomicAdd(&deg[d.z], 1);
        atomicAdd(&deg[d.w], 1);
    } else {
        for (int j = i; j < E; j++) atomicAdd(&deg[dst[j]], 1);
    }
}

__global__ void scan_reduce(const int* __restrict__ deg, int* __restrict__ bsum, int n) {
    __shared__ int sh[256];
    int tid = threadIdx.x;
    int base = blockIdx.x * 1024;
    int s = 0;
    for (int i = tid; i < 1024; i += 256) {
        int g = base + i;
        s += (g < n) ? deg[g] : 0;
    }
    sh[tid] = s; __syncthreads();
    for (int off = 128; off; off >>= 1) {
        if (tid < off) sh[tid] += sh[tid + off];
        __syncthreads();
    }
    if (tid == 0) bsum[blockIdx.x] = sh[0];
}

__global__ void scan_bsums(int* __restrict__ bsum, int B, int* __restrict__ rowptr, int n, int E) {
    __shared__ int sh[256];
    int tid = threadIdx.x;
    int v = (tid < B) ? bsum[tid] : 0;
    sh[tid] = v; __syncthreads();
    for (int off = 1; off < 256; off <<= 1) {
        int t = (tid >= off) ? sh[tid - off] : 0;
        __syncthreads();
        sh[tid] += t;
        __syncthreads();
    }
    if (tid < B) bsum[tid] = sh[tid] - v;
    if (tid == 0) rowptr[n] = E;
}

__global__ void scan_write(const int* __restrict__ deg, const int* __restrict__ boff,
                           int* __restrict__ rowptr, int* __restrict__ cursor, int n) {
    __shared__ int sh[256];
    int tid = threadIdx.x;
    int base = blockIdx.x * 1024 + tid * 4;
    int v[4]; int tsum = 0;
#pragma unroll
    for (int j = 0; j < 4; j++) {
        int g = base + j;
        v[j] = (g < n) ? deg[g] : 0;
        tsum += v[j];
    }
    sh[tid] = tsum; __syncthreads();
    for (int off = 1; off < 256; off <<= 1) {
        int t = (tid >= off) ? sh[tid - off] : 0;
        __syncthreads();
        sh[tid] += t;
        __syncthreads();
    }
    int run = boff[blockIdx.x] + sh[tid] - tsum;
#pragma unroll
    for (int j = 0; j < 4; j++) {
        int g = base + j;
        if (g < n) { rowptr[g] = run; cursor[g] = run; }
        run += v[j];
    }
}

__global__ void scatter4_kernel(const int* __restrict__ src, const int* __restrict__ dst,
                                int* __restrict__ cursor, int* __restrict__ srcs, int E) {
    int i = (blockIdx.x * blockDim.x + threadIdx.x) * 4;
    if (i + 3 < E) {
        int4 d = *(const int4*)(dst + i);
        int4 s = *(const int4*)(src + i);
        srcs[atomicAdd(&cursor[d.x], 1)] = s.x;
        srcs[atomicAdd(&cursor[d.y], 1)] = s.y;
        srcs[atomicAdd(&cursor[d.z], 1)] = s.z;
        srcs[atomicAdd(&cursor[d.w], 1)] = s.w;
    } else {
        for (int j = i; j < E; j++) {
            int p = atomicAdd(&cursor[dst[j]], 1);
            srcs[p] = src[j];
        }
    }
}

// ---------------- fp16 pack kernels ----------------
__global__ void packA16(const float* __restrict__ A, __half* __restrict__ A16, int total2) {
    int i = blockIdx.x * blockDim.x + threadIdx.x;
    if (i >= total2) return;
    float2 v = ((const float2*)A)[i];
    ((__half2*)A16)[i] = __floats2half2_rn(v.x, v.y);
}

__global__ void packW16(const float* __restrict__ W, __half* __restrict__ W16,
                        int K, int Ncols, int Npad, int interleave48) {
    int i = blockIdx.x * blockDim.x + threadIdx.x;
    if (i >= Npad * K) return;
    int r = i / K, c = i % K;
    int srcCol; bool valid;
    if (interleave48) {
        int hh = r / 48, cc = r % 48;
        srcCol = hh * 47 + cc;
        valid = (cc < 47);
    } else {
        srcCol = r;
        valid = (r < Ncols);
    }
    float v = valid ? W[(size_t)c * Ncols + srcCol] : 0.f;
    W16[i] = __float2half_rn(v);
}

// padded-col al for layer 2 (4 heads x 48, pad class = 0)
__global__ void pad_al(const float* __restrict__ a2l, float* __restrict__ alp) {
    int i = threadIdx.x;
    if (i < 192) {
        int hh = i / 48, cc = i % 48;
        alp[i] = (cc < 47) ? a2l[hh * 47 + cc] : 0.f;
    }
}

// ---------------- mma.sync fp16 GEMM, 4-stage cp.async, fused el epilogue ----------------
#define MMA_F16(c, a, b0, b1) \
    asm volatile("mma.sync.aligned.m16n8k16.row.col.f32.f16.f16.f32 " \
        "{%0,%1,%2,%3},{%4,%5,%6,%7},{%8,%9},{%0,%1,%2,%3};" \
        : "+f"((c)[0]), "+f"((c)[1]), "+f"((c)[2]), "+f"((c)[3]) \
        : "r"((a)[0]), "r"((a)[1]), "r"((a)[2]), "r"((a)[3]), "r"(b0), "r"(b1))

template <int NPAD, int MINB>
__global__ __launch_bounds__(256, MINB)
void mma_gemm(const __half* __restrict__ A16, const __half* __restrict__ B16,
              __half* __restrict__ C16, const float* __restrict__ alp,
              float* __restrict__ el, int n, int K, int Ncols) {
    constexpr int STR = 40;
    constexpr int NT = NPAD / 16;
    constexpr int BUFU = (128 + NPAD) * STR;   // ushorts per buffer
    extern __shared__ unsigned short sm[];
    const uint32_t sbase = smem_u32(sm);

    const int tid = threadIdx.x;
    const int warp = tid >> 5;
    const int lane = tid & 31;
    const int g = lane >> 2;
    const int t = lane & 3;
    const int wm = (warp >> 1) * 32;
    const int wn = (warp & 1) * (NPAD / 2);
    const int row0 = blockIdx.x * 128;

    float acc[2][NT][4] = {};
    const int nchunks = K >> 5;

    auto load_chunk = [&](int buf, int kc) {
        uint32_t bb = sbase + (uint32_t)buf * BUFU * 2;
#pragma unroll
        for (int i2 = 0; i2 < 2; i2++) {
            int i = tid + i2 * 256;
            int r = i >> 2, q = i & 3;
            int gr = row0 + r;
            bool ok = gr < n;
            size_t off = (size_t)(ok ? gr : 0) * K + (size_t)kc * 32 + q * 8;
            cp16(bb + (uint32_t)(r * STR + q * 8) * 2, A16 + off, ok);
        }
#pragma unroll
        for (int i2 = 0; i2 < NPAD / 64; i2++) {
            int i = tid + i2 * 256;
            int r = i >> 2, q = i & 3;
            size_t off = (size_t)r * K + (size_t)kc * 32 + q * 8;
            cp16(bb + (uint32_t)(5120 + r * STR + q * 8) * 2, B16 + off, true);
        }
        CP_COMMIT();
    };

    load_chunk(0, 0);
    load_chunk(1, 1);
    load_chunk(2, 2);

    for (int kc = 0; kc < nchunks; kc++) {
        if (kc + 3 < nchunks) load_chunk((kc + 3) & 3, kc + 3);
        else CP_COMMIT();
        CP_WAIT(3);
        __syncthreads();

        const unsigned short* As = sm + (kc & 3) * BUFU;
        const unsigned short* Bs = As + 5120;

#pragma unroll
        for (int kk = 0; kk < 32; kk += 16) {
            uint32_t a[2][4];
#pragma unroll
            for (int mt = 0; mt < 2; mt++) {
                int base = (wm + mt * 16 + g) * STR + kk + t * 2;
                a[mt][0] = *(const uint32_t*)&As[base];
                a[mt][1] = *(const uint32_t*)&As[base + 8 * STR];
                a[mt][2] = *(const uint32_t*)&As[base + 8];
                a[mt][3] = *(const uint32_t*)&As[base + 8 * STR + 8];
            }
#pragma unroll
            for (int j = 0; j < NT; j++) {
                int nb = (wn + j * 8 + g) * STR + kk + t * 2;
                uint32_t b0 = *(const uint32_t*)&Bs[nb];
                uint32_t b1 = *(const uint32_t*)&Bs[nb + 8];
#pragma unroll
                for (int mt = 0; mt < 2; mt++) {
                    MMA_F16(acc[mt][j], a[mt], b0, b1);
                }
            }
        }
        __syncthreads();
    }

    // ---- fused el: warp's NPAD/2 cols = exactly 2 heads (width NPAD/4 each) ----
    float elp[2][2][2] = {};   // [mt][rowhalf][head_local]
#pragma unroll
    for (int mt = 0; mt < 2; mt++) {
#pragma unroll
        for (int j = 0; j < NT; j++) {
            int lc = j * 8 + t * 2;
            int hl = lc / (NPAD / 4);
            int c = wn + lc;
            float a0 = __ldg(&alp[c]);
            float a1 = __ldg(&alp[c + 1]);
            elp[mt][0][hl] += acc[mt][j][0] * a0 + acc[mt][j][1] * a1;
            elp[mt][1][hl] += acc[mt][j][2] * a0 + acc[mt][j][3] * a1;
        }
    }
#pragma unroll
    for (int mt = 0; mt < 2; mt++)
#pragma unroll
        for (int rh = 0; rh < 2; rh++)
#pragma unroll
            for (int hl = 0; hl < 2; hl++) {
                elp[mt][rh][hl] += __shfl_xor_sync(0xffffffffu, elp[mt][rh][hl], 1);
                elp[mt][rh][hl] += __shfl_xor_sync(0xffffffffu, elp[mt][rh][hl], 2);
            }
    int hbase = (warp & 1) * 2;
    if (t == 0) {
#pragma unroll
        for (int mt = 0; mt < 2; mt++) {
            int r1 = row0 + wm + mt * 16 + g;
            int r2 = r1 + 8;
            if (r1 < n) *(float2*)(el + r1 * 4 + hbase)
                = make_float2(elp[mt][0][0], elp[mt][0][1]);
            if (r2 < n) *(float2*)(el + r2 * 4 + hbase)
                = make_float2(elp[mt][1][0], elp[mt][1][1]);
        }
    }

#pragma unroll
    for (int mt = 0; mt < 2; mt++) {
#pragma unroll
        for (int j = 0; j < NT; j++) {
            int r1 = row0 + wm + mt * 16 + g;
            int r2 = r1 + 8;
            int c = wn + j * 8 + t * 2;
            if (c < Ncols) {
                if (r1 < n) *(__half2*)(C16 + (size_t)r1 * Ncols + c)
                    = __floats2half2_rn(acc[mt][j][0], acc[mt][j][1]);
                if (r2 < n) *(__half2*)(C16 + (size_t)r2 * Ncols + c)
                    = __floats2half2_rn(acc[mt][j][2], acc[mt][j][3]);
            }
        }
    }
}

// ---------------- attention scalars ----------------
__global__ void wdr_kernel(const float* __restrict__ Wd, const float* __restrict__ ar,
                           float* __restrict__ wdr, int K, int D) {
    int idx = blockIdx.x * blockDim.x + threadIdx.x;
    if (idx >= K * 4) return;
    int k = idx >> 2, h = idx & 3;
    float s = 0.f;
    const float* wrow = Wd + (size_t)k * (4 * D) + h * D;
    const float* arow = ar + h * D;
    for (int d = 0; d < D; d++) s += wrow[d] * arow[d];
    wdr[k * 4 + h] = s;
}

__global__ void er_kernel(const float* __restrict__ hmat, const float* __restrict__ wdr,
                          float* __restrict__ er, int n, int K) {
    int wid = (blockIdx.x * blockDim.x + threadIdx.x) >> 5;
    int lane = threadIdx.x & 31;
    if (wid >= n) return;
    const float* hp = hmat + (size_t)wid * K;
    float a0 = 0, a1 = 0, a2 = 0, a3 = 0;
    for (int k = lane; k < K; k += 32) {
        float hv = hp[k];
        float4 w = ((const float4*)wdr)[k];
        a0 += hv * w.x; a1 += hv * w.y; a2 += hv * w.z; a3 += hv * w.w;
    }
#pragma unroll
    for (int off = 16; off; off >>= 1) {
        a0 += __shfl_xor_sync(0xffffffffu, a0, off);
        a1 += __shfl_xor_sync(0xffffffffu, a1, off);
        a2 += __shfl_xor_sync(0xffffffffu, a2, off);
        a3 += __shfl_xor_sync(0xffffffffu, a3, off);
    }
    if (lane == 0) {
        float4* o = (float4*)(er + (size_t)wid * 4);
        *o = make_float4(a0, a1, a2, a3);
    }
}

// ---------------- fused edge aggregation: 2 edges per warp iteration ----------------
__global__ __launch_bounds__(256)
void agg_fused(const __half* __restrict__ fs16, const float* __restrict__ el,
               const float* __restrict__ er, const int* __restrict__ rowptr,
               const int* __restrict__ srcs, const float* __restrict__ bias,
               float* __restrict__ out, __half* __restrict__ oh, int n) {
    int node = blockIdx.x * 8 + (threadIdx.x >> 5);
    if (node >= n) return;
    int lane = threadIdx.x & 31;
    int half_ = lane >> 4;
    int sub = lane & 15;
    int h = sub >> 2;
    int s0 = rowptr[node], s1 = rowptr[node + 1];
    float ern = __ldg(&er[node * 4 + h]);
    float acc[8] = {};
    float den = 0.f;
    for (int base = s0; base < s1; base += 32) {
        int idx = base + lane;
        int sv = (idx < s1) ? __ldg(&srcs[idx]) : 0;
        int cnt = s1 - base; if (cnt > 32) cnt = 32;
        for (int i = 0; i < cnt; i += 8) {
#pragma unroll
            for (int u = 0; u < 8; u += 2) {
                int j = i + u + half_;
                bool ok = j < cnt;
                int s = __shfl_sync(0xffffffffu, sv, j & 31);
                if (!ok) s = 0;
                float ee = __ldg(&el[s * 4 + h]) + ern;
                ee = ee > 0.f ? ee : NEG_SLOPE * ee;
                float w = ok ? __expf(ee) : 0.f;
                den += w;
                uint4 raw = __ldg((const uint4*)(fs16 + (size_t)s * 128) + sub);
                float2 f0 = __half22float2(*(__half2*)&raw.x);
                float2 f1 = __half22float2(*(__half2*)&raw.y);
                float2 f2 = __half22float2(*(__half2*)&raw.z);
                float2 f3 = __half22float2(*(__half2*)&raw.w);
                acc[0] += w * f0.x; acc[1] += w * f0.y;
                acc[2] += w * f1.x; acc[3] += w * f1.y;
                acc[4] += w * f2.x; acc[5] += w * f2.y;
                acc[6] += w * f3.x; acc[7] += w * f3.y;
            }
        }
    }
    den += __shfl_xor_sync(0xffffffffu, den, 16);
#pragma unroll
    for (int k = 0; k < 8; k++) acc[k] += __shfl_xor_sync(0xffffffffu, acc[k], 16);
    float inv = (s1 > s0) ? (1.f / den) : 0.f;
    if (lane < 16) {
        const float* bp = bias + sub * 8;
        float o[8];
#pragma unroll
        for (int k = 0; k < 8; k++) o[k] = fmaxf(acc[k] * inv + __ldg(&bp[k]), 0.f);
        float4* hb = (float4*)(out + (size_t)node * 128 + sub * 8);
        hb[0] = make_float4(o[0], o[1], o[2], o[3]);
        hb[1] = make_float4(o[4], o[5], o[6], o[7]);
        __half2 u0 = __floats2half2_rn(o[0], o[1]);
        __half2 u1 = __floats2half2_rn(o[2], o[3]);
        __half2 u2 = __floats2half2_rn(o[4], o[5]);
        __half2 u3 = __floats2half2_rn(o[6], o[7]);
        uint4 pack;
        pack.x = *(uint32_t*)&u0; pack.y = *(uint32_t*)&u1;
        pack.z = *(uint32_t*)&u2; pack.w = *(uint32_t*)&u3;
        *(uint4*)(oh + (size_t)node * 128 + sub * 8) = pack;
    }
}

// ---------------- layer 2: 2 edges/warp iter, 16 lanes/edge, 12 halves/lane ----------------
__global__ __launch_bounds__(256)
void agg_final2(const __half* __restrict__ fs16, const float* __restrict__ el,
                const float* __restrict__ er, const int* __restrict__ rowptr,
                const int* __restrict__ srcs, const float* __restrict__ b2,
                float* __restrict__ out, int n) {
    int node = blockIdx.x * 8 + (threadIdx.x >> 5);
    if (node >= n) return;
    int lane = threadIdx.x & 31;
    int half_ = lane >> 4;
    int sub = lane & 15;
    int h = sub >> 2;
    int s0 = rowptr[node], s1 = rowptr[node + 1];
    float ern = __ldg(&er[node * 4 + h]);
    float acc[12] = {};
    float den = 0.f;
    for (int base = s0; base < s1; base += 32) {
        int idx = base + lane;
        int sv = (idx < s1) ? __ldg(&srcs[idx]) : 0;
        int cnt = s1 - base; if (cnt > 32) cnt = 32;
        for (int i = 0; i < cnt; i += 4) {
#pragma unroll
            for (int u = 0; u < 4; u += 2) {
                int j = i + u + half_;
                bool ok = j < cnt;
                int s = __shfl_sync(0xffffffffu, sv, j & 31);
                if (!ok) s = 0;
                float ee = __ldg(&el[s * 4 + h]) + ern;
                ee = ee > 0.f ? ee : NEG_SLOPE * ee;
                float w = ok ? __expf(ee) : 0.f;
                den += w;
                const uint2* p = (const uint2*)(fs16 + (size_t)s * 192 + sub * 12);
                uint2 q0 = __ldg(p), q1 = __ldg(p + 1), q2 = __ldg(p + 2);
                float2 f;
                f = __half22float2(*(__half2*)&q0.x); acc[0] += w * f.x; acc[1] += w * f.y;
                f = __half22float2(*(__half2*)&q0.y); acc[2] += w * f.x; acc[3] += w * f.y;
                f = __half22float2(*(__half2*)&q1.x); acc[4] += w * f.x; acc[5] += w * f.y;
                f = __half22float2(*(__half2*)&q1.y); acc[6] += w * f.x; acc[7] += w * f.y;
                f = __half22float2(*(__half2*)&q2.x); acc[8] += w * f.x; acc[9] += w * f.y;
                f = __half22float2(*(__half2*)&q2.y); acc[10] += w * f.x; acc[11] += w * f.y;
            }
        }
    }
    den += __shfl_xor_sync(0xffffffffu, den, 16);
#pragma unroll
    for (int k = 0; k < 12; k++) acc[k] += __shfl_xor_sync(0xffffffffu, acc[k], 16);
    float inv = (s1 > s0) ? (1.f / den) : 0.f;
    int cbase = (sub & 3) * 12;
    float v[12];
#pragma unroll
    for (int k = 0; k < 12; k++) {
        int c = cbase + k;
        v[k] = acc[k] * inv + ((c < 47) ? __ldg(&b2[h * 47 + c]) : 0.f);
    }
#pragma unroll
    for (int k = 0; k < 12; k++) {
        v[k] += __shfl_xor_sync(0xffffffffu, v[k], 4);
        v[k] += __shfl_xor_sync(0xffffffffu, v[k], 8);
        v[k] *= 0.25f;
    }
    float mx = -1e30f;
#pragma unroll
    for (int k = 0; k < 12; k++)
        if (cbase + k < 47) mx = fmaxf(mx, v[k]);
    mx = fmaxf(mx, __shfl_xor_sync(0xffffffffu, mx, 1));
    mx = fmaxf(mx, __shfl_xor_sync(0xffffffffu, mx, 2));
    float se = 0.f;
#pragma unroll
    for (int k = 0; k < 12; k++)
        if (cbase + k < 47) se += __expf(v[k] - mx);
    se += __shfl_xor_sync(0xffffffffu, se, 1);
    se += __shfl_xor_sync(0xffffffffu, se, 2);
    float l = logf(se) + mx;
    if (lane < 4) {
        float* op = out + (size_t)node * 47;
#pragma unroll
        for (int k = 0; k < 12; k++) {
            int c = cbase + k;
            if (c < 47) op[c] = v[k] - l;
        }
    }
}

// ---------------- launch (stream-forked DAG) ----------------
extern "C" void kernel_launch(void* const* d_in, const int* in_sizes, int n_in,
                              void* d_out, int out_size) {
    const float* x   = (const float*)d_in[0];
    const int*   src = (const int*)d_in[1];
    const int*   dst = (const int*)d_in[2];
    const float* W0s = (const float*)d_in[3];
    const float* W0d = (const float*)d_in[4];
    const float* a0l = (const float*)d_in[5];
    const float* a0r = (const float*)d_in[6];
    const float* b0  = (const float*)d_in[7];
    const float* W1s = (const float*)d_in[8];
    const float* W1d = (const float*)d_in[9];
    const float* a1l = (const float*)d_in[10];
    const float* a1r = (const float*)d_in[11];
    const float* b1  = (const float*)d_in[12];
    const float* W2s = (const float*)d_in[13];
    const float* W2d = (const float*)d_in[14];
    const float* a2l = (const float*)d_in[15];
    const float* a2r = (const float*)d_in[16];
    const float* b2  = (const float*)d_in[17];

    int n = in_sizes[0] / 256;
    int E = in_sizes[1];
    float* out = (float*)d_out;

    float *hbuf, *el, *er, *wdr, *alp;
    __half *fs16, *a16, *w16;
    int *deg, *rowptr, *cursor, *srcs, *bsum;
    cudaGetSymbolAddress((void**)&fs16,   g_fs16);
    cudaGetSymbolAddress((void**)&hbuf,   g_h);
    cudaGetSymbolAddress((void**)&el,     g_el);
    cudaGetSymbolAddress((void**)&er,     g_er);
    cudaGetSymbolAddress((void**)&wdr,    g_wdr);
    cudaGetSymbolAddress((void**)&alp,    g_alp);
    cudaGetSymbolAddress((void**)&deg,    g_deg);
    cudaGetSymbolAddress((void**)&rowptr, g_rowptr);
    cudaGetSymbolAddress((void**)&cursor, g_cursor);
    cudaGetSymbolAddress((void**)&srcs,   g_srcs);
    cudaGetSymbolAddress((void**)&bsum,   g_bsum);
    cudaGetSymbolAddress((void**)&a16,    g_a16);
    cudaGetSymbolAddress((void**)&w16,    g_w16);

    const int smem128 = 4 * (128 + 128) * 40 * 2;  // 81920 B
    const int smem192 = 4 * (128 + 192) * 40 * 2;  // 102400 B
    cudaFuncSetAttribute((const void*)mma_gemm<128, 2>,
                         cudaFuncAttributeMaxDynamicSharedMemorySize, smem128);
    cudaFuncSetAttribute((const void*)mma_gemm<192, 2>,
                         cudaFuncAttributeMaxDynamicSharedMemorySize, smem192);

    int gemmBlocks = (n + 127) / 128;
    int nodeBlocks = (n + 7) / 8;
    int nb = (n + 1023) / 1024;
    int e4Blocks = (E / 4 + 255) / 256;

    // side stream + events
    cudaStream_t sB;
    cudaStreamCreate(&sB);
    cudaEvent_t evFork, evWdr0, evSide0, evG0, evW1, evG1, evEr1s, evAgg1, evW2, evEr2s;
    cudaEventCreateWithFlags(&evFork,  cudaEventDisableTiming);
    cudaEventCreateWithFlags(&evWdr0,  cudaEventDisableTiming);
    cudaEventCreateWithFlags(&evSide0, cudaEventDisableTiming);
    cudaEventCreateWithFlags(&evG0,    cudaEventDisableTiming);
    cudaEventCreateWithFlags(&evW1,    cudaEventDisableTiming);
    cudaEventCreateWithFlags(&evG1,    cudaEventDisableTiming);
    cudaEventCreateWithFlags(&evEr1s,  cudaEventDisableTiming);
    cudaEventCreateWithFlags(&evAgg1,  cudaEventDisableTiming);
    cudaEventCreateWithFlags(&evW2,    cudaEventDisableTiming);
    cudaEventCreateWithFlags(&evEr2s,  cudaEventDisableTiming);

    // ---- fork ----
    cudaEventRecord(evFork, 0);
    cudaStreamWaitEvent(sB, evFork, 0);

    // main: layer-0 dense chain (gemm also emits el)
    wdr_kernel<<<(256 * 4 + 255) / 256, 256>>>(W0d, a0r, wdr, 256, 32);
    cudaEventRecord(evWdr0, 0);
    packA16<<<(n * 256 / 2 + 255) / 256, 256>>>(x, a16, n * 256 / 2);
    packW16<<<(128 * 256 + 255) / 256, 256>>>(W0s, w16, 256, 128, 128, 0);
    mma_gemm<128, 2><<<gemmBlocks, 256, smem128>>>(a16, w16, fs16, a0l, el, n, 256, 128);
    cudaEventRecord(evG0, 0);

    // side: CSR build, then er0
    zero_i32<<<(n + 255) / 256, 256, 0, sB>>>(deg, n);
    hist4_kernel<<<e4Blocks, 256, 0, sB>>>(dst, deg, E);
    scan_reduce<<<nb, 256, 0, sB>>>(deg, bsum, n);
    scan_bsums<<<1, 256, 0, sB>>>(bsum, nb, rowptr, n, E);
    scan_write<<<nb, 256, 0, sB>>>(deg, bsum, rowptr, cursor, n);
    scatter4_kernel<<<e4Blocks, 256, 0, sB>>>(src, dst, cursor, srcs, E);
    cudaStreamWaitEvent(sB, evWdr0, 0);
    er_kernel<<<nodeBlocks, 256, 0, sB>>>(x, wdr, er, n, 256);
    cudaEventRecord(evSide0, sB);

    // side: layer-1 weight prep (after gemm0 frees w16)
    cudaStreamWaitEvent(sB, evG0, 0);
    wdr_kernel<<<(128 * 4 + 255) / 256, 256, 0, sB>>>(W1d, a1r, wdr, 128, 32);
    packW16<<<(128 * 128 + 255) / 256, 256, 0, sB>>>(W1s, w16, 128, 128, 128, 0);
    cudaEventRecord(evW1, sB);

    // main: join, agg0
    cudaStreamWaitEvent(0, evSide0, 0);
    agg_fused<<<nodeBlocks, 256>>>(fs16, el, er, rowptr, srcs, b0, hbuf, a16, n);

    // ---- layer 1 ----
    cudaStreamWaitEvent(0, evW1, 0);
    mma_gemm<128, 2><<<gemmBlocks, 256, smem128>>>(a16, w16, fs16, a1l, el, n, 128, 128);
    cudaEventRecord(evG1, 0);

    // side: er1, then layer-2 weight prep (incl. padded al2)
    cudaStreamWaitEvent(sB, evG1, 0);
    er_kernel<<<nodeBlocks, 256, 0, sB>>>(hbuf, wdr, er, n, 128);
    cudaEventRecord(evEr1s, sB);
    wdr_kernel<<<(128 * 4 + 255) / 256, 256, 0, sB>>>(W2d, a2r, wdr, 128, 47);
    packW16<<<(192 * 128 + 255) / 256, 256, 0, sB>>>(W2s, w16, 128, 188, 192, 1);
    pad_al<<<1, 192, 0, sB>>>(a2l, alp);
    cudaEventRecord(evW2, sB);

    // main: join er1, agg1
    cudaStreamWaitEvent(0, evEr1s, 0);
    agg_fused<<<nodeBlocks, 256>>>(fs16, el, er, rowptr, srcs, b1, hbuf, a16, n);
    cudaEventRecord(evAgg1, 0);

    // side: er2 concurrent with gemm2
    cudaStreamWaitEvent(sB, evAgg1, 0);
    er_kernel<<<nodeBlocks, 256, 0, sB>>>(hbuf, wdr, er, n, 128);
    cudaEventRecord(evEr2s, sB);

    // ---- layer 2 ----
    cudaStreamWaitEvent(0, evW2, 0);
    mma_gemm<192, 2><<<gemmBlocks, 256, smem192>>>(a16, w16, fs16, alp, el, n, 128, 192);
    cudaStreamWaitEvent(0, evEr2s, 0);
    agg_final2<<<nodeBlocks, 256>>>(fs16, el, er, rowptr, srcs, b2, out, n);

    cudaEventDestroy(evFork);
    cudaEventDestroy(evWdr0);
    cudaEventDestroy(evSide0);
    cudaEventDestroy(evG0);
    cudaEventDestroy(evW1);
    cudaEventDestroy(evG1);
    cudaEventDestroy(evEr1s);
    cudaEventDestroy(evAgg1);
    cudaEventDestroy(evW2);
    cudaEventDestroy(evEr2s);
    cudaStreamDestroy(sB);
}